// round 1
// baseline (speedup 1.0000x reference)
#include <cuda_runtime.h>
#include <cstdint>

#define Nn   8192
#define Ee   262144
#define Tt   2048
#define NBLK 148
#define NMAT 147
#define NTHR 512

// ---- scratch (no allocation allowed: device globals) ----
__device__ float g_v[Nn];        // xTB - x
__device__ float g_x1[Nn];       // edge scatter result
__device__ float g_x21[Nn];      // W2@v + b2
__device__ float g_x2[Nn];       // W3@x21 + b3
__device__ float g_h[Tt * 8];    // LSTM hidden states
__device__ int   g_bar1;         // barrier between matvec1 and matvec2
__device__ int   g_done;         // matvec blocks finished

__device__ __forceinline__ float tanhap(float x) {
    float y;
    asm("tanh.approx.f32 %0, %1;" : "=f"(y) : "f"(x));
    return y;
}

// ---------------------------------------------------------------------------
// K0: init — zero scatter buffer + flags, compute v = xTB - x
// ---------------------------------------------------------------------------
__global__ void gl_init(const float* __restrict__ x, const float* __restrict__ xTB) {
    int i = blockIdx.x * blockDim.x + threadIdx.x;
    if (i < Nn) {
        g_v[i]  = xTB[i] - x[i];
        g_x1[i] = 0.f;
    }
    if (i == 0) { g_bar1 = 0; g_done = 0; }
}

// warp-per-row matvec: vout[row] = W[row,:]·vin + b[row]
__device__ __forceinline__ void matvec_rows(const float* __restrict__ W,
                                            const float* __restrict__ vin,
                                            const float* __restrict__ b,
                                            float* __restrict__ vout,
                                            int gw, int nw, int lane) {
    const float4* vv = (const float4*)vin;
    for (int row = gw; row < Nn; row += nw) {
        const float4* wr = (const float4*)(W + (size_t)row * Nn);
        float acc0 = 0.f, acc1 = 0.f;
        #pragma unroll 4
        for (int j = lane; j < Nn / 4; j += 64) {
            float4 w0 = __ldg(wr + j);
            float4 u0 = __ldg(vv + j);
            float4 w1 = __ldg(wr + j + 32);
            float4 u1 = __ldg(vv + j + 32);
            acc0 += w0.x * u0.x + w0.y * u0.y + w0.z * u0.z + w0.w * u0.w;
            acc1 += w1.x * u1.x + w1.y * u1.y + w1.z * u1.z + w1.w * u1.w;
        }
        float acc = acc0 + acc1;
        #pragma unroll
        for (int o = 16; o; o >>= 1) acc += __shfl_down_sync(0xffffffffu, acc, o);
        if (lane == 0) vout[row] = acc + b[row];
    }
}

// ---------------------------------------------------------------------------
// K1: mega kernel.
//   blocks 0..146 : edge scatter, matvec1, barrier, matvec2, signal done
//   block  147    : LSTM recurrence (warp 0), W1 dot, wait, final combine
// ---------------------------------------------------------------------------
__global__ void __launch_bounds__(NTHR, 1)
gl_main(const float* __restrict__ x,   const float* __restrict__ cur,
        const int*   __restrict__ ei,  const float* __restrict__ att,
        const float* __restrict__ W2,  const float* __restrict__ b2,
        const float* __restrict__ W3,  const float* __restrict__ b3,
        const float* __restrict__ Wih, const float* __restrict__ Whh,
        const float* __restrict__ bih, const float* __restrict__ bhh,
        const float* __restrict__ W1,  const float* __restrict__ b1,
        const float* __restrict__ x30, float* __restrict__ out) {
    __shared__ float s_cur[Tt + 8];
    __shared__ float s_red[16];
    __shared__ float s_x3;

    const int lane = threadIdx.x & 31;
    const int warp = threadIdx.x >> 5;

    if (blockIdx.x < NMAT) {
        // ---------------- matvec / scatter blocks ----------------
        // edge scatter: msg = (x[src]-x[dst])*att[e] accumulated at dst
        {
            int tid  = blockIdx.x * NTHR + threadIdx.x;
            int nthr = NMAT * NTHR;
            for (int e = tid; e < Ee; e += nthr) {
                int s = ei[e];
                int d = ei[Ee + e];
                float m = (__ldg(x + s) - __ldg(x + d)) * __ldg(att + e);
                atomicAdd(&g_x1[d], m);
            }
        }

        int gw = blockIdx.x * (NTHR / 32) + warp;
        int nw = NMAT * (NTHR / 32);

        matvec_rows(W2, g_v, b2, g_x21, gw, nw, lane);

        // inter-block barrier among the NMAT matvec blocks
        __syncthreads();
        if (threadIdx.x == 0) {
            __threadfence();
            atomicAdd(&g_bar1, 1);
            while (atomicAdd(&g_bar1, 0) < NMAT) {}
            __threadfence();
        }
        __syncthreads();

        matvec_rows(W3, g_x21, b3, g_x2, gw, nw, lane);

        __syncthreads();
        if (threadIdx.x == 0) {
            __threadfence();
            atomicAdd(&g_done, 1);
        }
    } else {
        // ---------------- LSTM block ----------------
        for (int i = threadIdx.x; i < Tt; i += NTHR) s_cur[i] = cur[i];
        if (threadIdx.x < 8) s_cur[Tt + threadIdx.x] = 0.f;
        __syncthreads();

        if (warp == 0) {
            const int u = lane & 7;
            // preload & prescale weights (sigmoid(z) = 0.5*tanh(z/2)+0.5 -> fold 0.5 in)
            float wi[8], wf[8], wg[8], wo[8];
            #pragma unroll
            for (int j = 0; j < 8; j++) {
                wi[j] = 0.5f * Whh[(u)      * 8 + j];
                wf[j] = 0.5f * Whh[(8 + u)  * 8 + j];
                wg[j] =        Whh[(16 + u) * 8 + j];
                wo[j] = 0.5f * Whh[(24 + u) * 8 + j];
            }
            float ai = 0.5f * Wih[u],      bi2 = 0.5f * (bih[u]      + bhh[u]);
            float af = 0.5f * Wih[8 + u],  bf2 = 0.5f * (bih[8 + u]  + bhh[8 + u]);
            float ag =        Wih[16 + u], bg2 =        (bih[16 + u] + bhh[16 + u]);
            float ao = 0.5f * Wih[24 + u], bo2 = 0.5f * (bih[24 + u] + bhh[24 + u]);

            float h = 0.f, c = 0.f;
            float xt = s_cur[0];
            float* ghp = g_h + u;

            #pragma unroll 1
            for (int t = 0; t < Tt; t++) {
                // broadcast hidden state (lanes 0..7 hold units 0..7)
                float h0 = __shfl_sync(0xffffffffu, h, 0);
                float h1 = __shfl_sync(0xffffffffu, h, 1);
                float h2 = __shfl_sync(0xffffffffu, h, 2);
                float h3 = __shfl_sync(0xffffffffu, h, 3);
                float h4 = __shfl_sync(0xffffffffu, h, 4);
                float h5 = __shfl_sync(0xffffffffu, h, 5);
                float h6 = __shfl_sync(0xffffffffu, h, 6);
                float h7 = __shfl_sync(0xffffffffu, h, 7);

                float xn = s_cur[t + 1];                 // prefetch next input
                float pi = fmaf(ai, xt, bi2);
                float pf = fmaf(af, xt, bf2);
                float pg = fmaf(ag, xt, bg2);
                float po = fmaf(ao, xt, bo2);

                // 2-accumulator dots per gate
                float ia = fmaf(wi[0], h0, pi), ib = wi[4] * h4;
                float fa = fmaf(wf[0], h0, pf), fb = wf[4] * h4;
                float ga = fmaf(wg[0], h0, pg), gb = wg[4] * h4;
                float oa = fmaf(wo[0], h0, po), ob = wo[4] * h4;
                ia = fmaf(wi[1], h1, ia); ib = fmaf(wi[5], h5, ib);
                fa = fmaf(wf[1], h1, fa); fb = fmaf(wf[5], h5, fb);
                ga = fmaf(wg[1], h1, ga); gb = fmaf(wg[5], h5, gb);
                oa = fmaf(wo[1], h1, oa); ob = fmaf(wo[5], h5, ob);
                ia = fmaf(wi[2], h2, ia); ib = fmaf(wi[6], h6, ib);
                fa = fmaf(wf[2], h2, fa); fb = fmaf(wf[6], h6, fb);
                ga = fmaf(wg[2], h2, ga); gb = fmaf(wg[6], h6, gb);
                oa = fmaf(wo[2], h2, oa); ob = fmaf(wo[6], h6, ob);
                ia = fmaf(wi[3], h3, ia); ib = fmaf(wi[7], h7, ib);
                fa = fmaf(wf[3], h3, fa); fb = fmaf(wf[7], h7, fb);
                ga = fmaf(wg[3], h3, ga); gb = fmaf(wg[7], h7, gb);
                oa = fmaf(wo[3], h3, oa); ob = fmaf(wo[7], h7, ob);

                float di = ia + ib, df = fa + fb, dg = ga + gb, dq = oa + ob;

                float si = fmaf(tanhap(di), 0.5f, 0.5f);
                float sf = fmaf(tanhap(df), 0.5f, 0.5f);
                float tg = tanhap(dg);
                float so = fmaf(tanhap(dq), 0.5f, 0.5f);

                c = fmaf(sf, c, si * tg);
                h = so * tanhap(c);

                if (lane < 8) ghp[t * 8] = h;
                xt = xn;
            }
        }
        __syncthreads();   // g_h visible block-wide

        // x3 scalar = W1 · hs_flat + b1
        float part = 0.f;
        for (int k = threadIdx.x; k < Tt * 8; k += NTHR)
            part = fmaf(__ldg(W1 + k), g_h[k], part);
        #pragma unroll
        for (int o = 16; o; o >>= 1) part += __shfl_down_sync(0xffffffffu, part, o);
        if (lane == 0) s_red[warp] = part;
        __syncthreads();
        if (threadIdx.x == 0) {
            float s = 0.f;
            #pragma unroll
            for (int w = 0; w < 16; w++) s += s_red[w];
            s_x3 = s + b1[0];
            while (atomicAdd(&g_done, 0) < NMAT) {}  // wait for matvec/scatter blocks
            __threadfence();
        }
        __syncthreads();

        float x3 = s_x3;
        for (int i = threadIdx.x; i < Nn; i += NTHR)
            out[i] = x[i] + g_x1[i] + g_x2[i] + x3 * x30[i];
    }
}

// ---------------------------------------------------------------------------
extern "C" void kernel_launch(void* const* d_in, const int* in_sizes, int n_in,
                              void* d_out, int out_size) {
    const float* x   = (const float*)d_in[0];
    const float* xTB = (const float*)d_in[1];
    const float* cur = (const float*)d_in[2];
    const int*   ei  = (const int*)  d_in[3];
    const float* att = (const float*)d_in[4];
    const float* W2  = (const float*)d_in[5];
    const float* b2  = (const float*)d_in[6];
    const float* W3  = (const float*)d_in[7];
    const float* b3  = (const float*)d_in[8];
    const float* Wih = (const float*)d_in[9];
    const float* Whh = (const float*)d_in[10];
    const float* bih = (const float*)d_in[11];
    const float* bhh = (const float*)d_in[12];
    const float* W1  = (const float*)d_in[13];
    const float* b1  = (const float*)d_in[14];
    const float* x30 = (const float*)d_in[15];
    float* out = (float*)d_out;

    gl_init<<<(Nn + 255) / 256, 256>>>(x, xTB);
    gl_main<<<NBLK, NTHR>>>(x, cur, ei, att, W2, b2, W3, b3,
                            Wih, Whh, bih, bhh, W1, b1, x30, out);
}